// round 1
// baseline (speedup 1.0000x reference)
#include <cuda_runtime.h>
#include <math.h>

// Problem constants
#define Bb   32
#define Ss   512
#define Dd   512
#define Hh   8
#define HDd  64
#define Ee   8
#define FFNf 2048
#define Tt   (Bb*Ss)     // 16384 tokens

// ---------------------------------------------------------------------------
// Scratch (device globals; no allocations allowed)
// ---------------------------------------------------------------------------
__device__ float g_q[Tt*Dd];
__device__ float g_k[Tt*Dd];
__device__ float g_v[Tt*Dd];
__device__ float g_attn[Tt*Dd];
__device__ float g_proj[Tt*Dd];
__device__ float g_h1[Tt*Dd];
__device__ float g_moe[Tt*Dd];
__device__ float g_router[Tt*Ee];
__device__ float g_hbuf[Tt*2*FFNf];     // 32768 x 2048 fp32 = 268 MB (indexed by token*2+k)
__device__ int   g_cnt[Ee];
__device__ int   g_tok[Ee*Tt];
__device__ float g_wt[Ee*Tt];
__device__ float g_rsum[Ee];

// ---------------------------------------------------------------------------
// zero scratch that is accumulated into
// ---------------------------------------------------------------------------
__global__ void zero_kernel() {
    int i = blockIdx.x * 256 + threadIdx.x;   // grid = Tt*Dd/256
    g_moe[i] = 0.0f;
    if (i < Ee) g_cnt[i] = 0;
}

// ---------------------------------------------------------------------------
// Generic C = A * W^T + bias   (A: [M,K], W: [N,K], N=512)
// 64x64 tile, BK=16, 256 threads, 4x4 per thread.
// asel: 0 -> A = Aext, 1 -> A = g_attn
// dsel: 0 g_q, 1 g_k, 2 g_v, 3 g_proj
// ---------------------------------------------------------------------------
__global__ void gemm_bias(const float* __restrict__ Aext, int asel,
                          const float* __restrict__ W,
                          const float* __restrict__ bias,
                          int dsel, int K) {
    const float* A = asel ? g_attn : Aext;
    float* C = (dsel == 0) ? g_q : (dsel == 1) ? g_k : (dsel == 2) ? g_v : g_proj;
    const int N = 512;

    __shared__ float As[16][64];
    __shared__ float Ws[16][64];

    int tid = threadIdx.x;
    int m0 = blockIdx.x * 64, n0 = blockIdx.y * 64;
    int lr = tid >> 2, lc = (tid & 3) * 4;
    int tm = (tid >> 4) * 4, tn = (tid & 15) * 4;

    const float* Ap = A + (size_t)(m0 + lr) * K + lc;
    const float* Wp = W + (size_t)(n0 + lr) * K + lc;

    float acc[4][4] = {};
    for (int k0 = 0; k0 < K; k0 += 16) {
        float4 a = *(const float4*)(Ap + k0);
        float4 w = *(const float4*)(Wp + k0);
        As[lc+0][lr] = a.x; As[lc+1][lr] = a.y; As[lc+2][lr] = a.z; As[lc+3][lr] = a.w;
        Ws[lc+0][lr] = w.x; Ws[lc+1][lr] = w.y; Ws[lc+2][lr] = w.z; Ws[lc+3][lr] = w.w;
        __syncthreads();
#pragma unroll
        for (int kk = 0; kk < 16; kk++) {
            float4 av = *(const float4*)&As[kk][tm];
            float4 wv = *(const float4*)&Ws[kk][tn];
            acc[0][0] += av.x*wv.x; acc[0][1] += av.x*wv.y; acc[0][2] += av.x*wv.z; acc[0][3] += av.x*wv.w;
            acc[1][0] += av.y*wv.x; acc[1][1] += av.y*wv.y; acc[1][2] += av.y*wv.z; acc[1][3] += av.y*wv.w;
            acc[2][0] += av.z*wv.x; acc[2][1] += av.z*wv.y; acc[2][2] += av.z*wv.z; acc[2][3] += av.z*wv.w;
            acc[3][0] += av.w*wv.x; acc[3][1] += av.w*wv.y; acc[3][2] += av.w*wv.z; acc[3][3] += av.w*wv.w;
        }
        __syncthreads();
    }
#pragma unroll
    for (int i = 0; i < 4; i++) {
        size_t crow = (size_t)(m0 + tm + i) * N + n0;
#pragma unroll
        for (int j = 0; j < 4; j++)
            C[crow + tn + j] = acc[i][j] + bias[n0 + tn + j];
    }
}

// ---------------------------------------------------------------------------
// Partial RoPE (first 32 of each 64-dim head; half=16), applied to q and k.
// ---------------------------------------------------------------------------
__global__ void rope_kernel() {
    int idx = blockIdx.x * 256 + threadIdx.x;        // grid covers Tt*Hh*16
    if (idx >= Tt * Hh * 16) return;
    int i = idx & 15;
    int h = (idx >> 4) & 7;
    int t = idx >> 7;
    int spos = t & (Ss - 1);                          // t = b*S + s
    float inv = powf(10000.0f, -(float)i * 2.0f / 32.0f);
    float ang = (float)spos * inv;
    float sn, cs;
    sincosf(ang, &sn, &cs);
    int base = t * Dd + h * 64;
    float x1 = g_q[base + i], x2 = g_q[base + 16 + i];
    g_q[base + i]      = x1 * cs - x2 * sn;
    g_q[base + 16 + i] = x2 * cs + x1 * sn;
    x1 = g_k[base + i]; x2 = g_k[base + 16 + i];
    g_k[base + i]      = x1 * cs - x2 * sn;
    g_k[base + 16 + i] = x2 * cs + x1 * sn;
}

// ---------------------------------------------------------------------------
// Flash attention: grid (S/64, H, B), 64 threads; each thread owns one q row.
// ---------------------------------------------------------------------------
__global__ void __launch_bounds__(64) attn_kernel() {
    __shared__ float Ks[32][64];
    __shared__ float Vs[32][64];

    int qt = blockIdx.x, h = blockIdx.y, b = blockIdx.z;
    int r = threadIdx.x;
    int srow = qt * 64 + r;
    const float* qp = g_q + (size_t)(b * Ss + srow) * Dd + h * 64;

    float q[64];
#pragma unroll
    for (int d = 0; d < 64; d++) q[d] = qp[d] * 0.125f;   // HD^-0.5

    float o[64];
#pragma unroll
    for (int d = 0; d < 64; d++) o[d] = 0.0f;
    float m = -1e30f, l = 0.0f;

    for (int j0 = 0; j0 < Ss; j0 += 32) {
        for (int i = 0; i < 32; i++) {
            Ks[i][r] = g_k[(size_t)(b * Ss + j0 + i) * Dd + h * 64 + r];
            Vs[i][r] = g_v[(size_t)(b * Ss + j0 + i) * Dd + h * 64 + r];
        }
        __syncthreads();

        float s[32];
#pragma unroll
        for (int c = 0; c < 32; c++) {
            float acc = 0.0f;
#pragma unroll
            for (int d = 0; d < 64; d++) acc += q[d] * Ks[c][d];
            s[c] = acc;
        }
        float tmax = m;
#pragma unroll
        for (int c = 0; c < 32; c++) tmax = fmaxf(tmax, s[c]);
        float scale = __expf(m - tmax);
        l *= scale;
#pragma unroll
        for (int d = 0; d < 64; d++) o[d] *= scale;
        m = tmax;
#pragma unroll
        for (int c = 0; c < 32; c++) {
            float p = __expf(s[c] - m);
            l += p;
            s[c] = p;
        }
#pragma unroll
        for (int c = 0; c < 32; c++) {
            float p = s[c];
#pragma unroll
            for (int d = 0; d < 64; d++) o[d] += p * Vs[c][d];
        }
        __syncthreads();
    }
    float inv = 1.0f / l;
    float* op = g_attn + (size_t)(b * Ss + srow) * Dd + h * 64;
#pragma unroll
    for (int d = 0; d < 64; d++) op[d] = o[d] * inv;
}

// ---------------------------------------------------------------------------
// out = LayerNorm(x + y) ; mode 0: x=ext(hidden_states), y=g_proj, out=g_h1
//                          mode 1: x=g_h1, y=g_moe, out=ext(d_out)
// ---------------------------------------------------------------------------
__global__ void add_ln(const float* __restrict__ xe,
                       const float* __restrict__ g, const float* __restrict__ bb,
                       float* __restrict__ oe, int mode) {
    const float* x; const float* y; float* o;
    if (mode == 0) { x = xe;   y = g_proj; o = g_h1; }
    else           { x = g_h1; y = g_moe;  o = oe;   }

    int row = blockIdx.x, tid = threadIdx.x;   // 128 threads
    size_t base = (size_t)row * Dd;
    float v[4]; float s = 0.0f, sq = 0.0f;
#pragma unroll
    for (int i = 0; i < 4; i++) {
        int c = tid + i * 128;
        float t = x[base + c] + y[base + c];
        v[i] = t; s += t; sq += t * t;
    }
#pragma unroll
    for (int off = 16; off; off >>= 1) {
        s  += __shfl_down_sync(0xffffffffu, s,  off);
        sq += __shfl_down_sync(0xffffffffu, sq, off);
    }
    __shared__ float rs[4], rq[4];
    int warp = tid >> 5, lane = tid & 31;
    if (lane == 0) { rs[warp] = s; rq[warp] = sq; }
    __syncthreads();
    if (tid == 0) {
        float S = rs[0] + rs[1] + rs[2] + rs[3];
        float Q = rq[0] + rq[1] + rq[2] + rq[3];
        rs[0] = S; rq[0] = Q;
    }
    __syncthreads();
    float mean = rs[0] * (1.0f / Dd);
    float var  = rq[0] * (1.0f / Dd) - mean * mean;
    float rstd = rsqrtf(var + 1e-5f);
#pragma unroll
    for (int i = 0; i < 4; i++) {
        int c = tid + i * 128;
        o[base + c] = (v[i] - mean) * rstd * g[c] + bb[c];
    }
}

// ---------------------------------------------------------------------------
// Router: one warp per token. softmax probs, top-2 (stable tie-break), lists.
// ---------------------------------------------------------------------------
__global__ void router_kernel(const float* __restrict__ gw) {
    int warp = threadIdx.x >> 5, lane = threadIdx.x & 31;
    int t = blockIdx.x * 4 + warp;
    const float* x = g_h1 + (size_t)t * Dd;
    float acc[8] = {};
    for (int d = lane; d < Dd; d += 32) {
        float xv = x[d];
#pragma unroll
        for (int e = 0; e < 8; e++) acc[e] += xv * gw[e * Dd + d];
    }
#pragma unroll
    for (int e = 0; e < 8; e++)
#pragma unroll
        for (int off = 16; off; off >>= 1)
            acc[e] += __shfl_xor_sync(0xffffffffu, acc[e], off);

    if (lane == 0) {
        float mx = acc[0];
#pragma unroll
        for (int e = 1; e < 8; e++) mx = fmaxf(mx, acc[e]);
        float p[8], sm = 0.0f;
#pragma unroll
        for (int e = 0; e < 8; e++) { p[e] = __expf(acc[e] - mx); sm += p[e]; }
        float inv = 1.0f / sm;
#pragma unroll
        for (int e = 0; e < 8; e++) { p[e] *= inv; g_router[t * 8 + e] = p[e]; }
        int i1 = 0;
#pragma unroll
        for (int e = 1; e < 8; e++) if (p[e] > p[i1]) i1 = e;
        int i2 = (i1 == 0) ? 1 : 0;
#pragma unroll
        for (int e = 0; e < 8; e++) if (e != i1 && p[e] > p[i2]) i2 = e;
        float wsum = p[i1] + p[i2];
        int s1 = atomicAdd(&g_cnt[i1], 1);
        g_tok[i1 * Tt + s1] = t * 2;     g_wt[i1 * Tt + s1] = p[i1] / wsum;
        int s2 = atomicAdd(&g_cnt[i2], 1);
        g_tok[i2 * Tt + s2] = t * 2 + 1; g_wt[i2 * Tt + s2] = p[i2] / wsum;
    }
}

// deterministic load-balance loss reduction
__global__ void lb1_kernel() {
    int e = blockIdx.x;
    float p = 0.0f;
    for (int t = threadIdx.x; t < Tt; t += 256) p += g_router[t * 8 + e];
    __shared__ float sm[256];
    sm[threadIdx.x] = p; __syncthreads();
    for (int s = 128; s; s >>= 1) {
        if (threadIdx.x < s) sm[threadIdx.x] += sm[threadIdx.x + s];
        __syncthreads();
    }
    if (threadIdx.x == 0) g_rsum[e] = sm[0];
}
__global__ void lb2_kernel(float* __restrict__ dst) {
    float acc = 0.0f;
#pragma unroll
    for (int e = 0; e < 8; e++) { float m = g_rsum[e] * (1.0f / Tt); acc += m * m; }
    *dst = 8.0f * acc;
}

// ---------------------------------------------------------------------------
// Grouped FFN1: h = gelu(x_tok @ W1[e]^T + b1[e]) -> g_hbuf[token*2+k]
// grid (Tt/64, FFN/64, E) with early exit past g_cnt[e].
// ---------------------------------------------------------------------------
__global__ void ffn1_kernel(const float* __restrict__ W1, const float* __restrict__ B1) {
    int e = blockIdx.z;
    int cnt = g_cnt[e];
    int m0 = blockIdx.x * 64;
    if (m0 >= cnt) return;
    int n0 = blockIdx.y * 64;
    const float* W = W1 + (size_t)e * FFNf * Dd;

    __shared__ float As[16][64];
    __shared__ float Ws[16][64];
    int tid = threadIdx.x;
    int lr = tid >> 2, lc = (tid & 3) * 4;
    int tm = (tid >> 4) * 4, tn = (tid & 15) * 4;

    int r = m0 + lr;
    int tok2 = (r < cnt) ? g_tok[e * Tt + r] : -1;
    const float* Ap = (tok2 >= 0) ? (g_h1 + (size_t)(tok2 >> 1) * Dd + lc) : g_h1;
    const float* Wp = W + (size_t)(n0 + lr) * Dd + lc;

    float acc[4][4] = {};
    for (int k0 = 0; k0 < Dd; k0 += 16) {
        float4 a = (tok2 >= 0) ? *(const float4*)(Ap + k0) : make_float4(0, 0, 0, 0);
        float4 w = *(const float4*)(Wp + k0);
        As[lc+0][lr] = a.x; As[lc+1][lr] = a.y; As[lc+2][lr] = a.z; As[lc+3][lr] = a.w;
        Ws[lc+0][lr] = w.x; Ws[lc+1][lr] = w.y; Ws[lc+2][lr] = w.z; Ws[lc+3][lr] = w.w;
        __syncthreads();
#pragma unroll
        for (int kk = 0; kk < 16; kk++) {
            float4 av = *(const float4*)&As[kk][tm];
            float4 wv = *(const float4*)&Ws[kk][tn];
            acc[0][0] += av.x*wv.x; acc[0][1] += av.x*wv.y; acc[0][2] += av.x*wv.z; acc[0][3] += av.x*wv.w;
            acc[1][0] += av.y*wv.x; acc[1][1] += av.y*wv.y; acc[1][2] += av.y*wv.z; acc[1][3] += av.y*wv.w;
            acc[2][0] += av.z*wv.x; acc[2][1] += av.z*wv.y; acc[2][2] += av.z*wv.z; acc[2][3] += av.z*wv.w;
            acc[3][0] += av.w*wv.x; acc[3][1] += av.w*wv.y; acc[3][2] += av.w*wv.z; acc[3][3] += av.w*wv.w;
        }
        __syncthreads();
    }
#pragma unroll
    for (int i = 0; i < 4; i++) {
        int rr = m0 + tm + i;
        if (rr < cnt) {
            int t2 = g_tok[e * Tt + rr];
            size_t crow = (size_t)t2 * FFNf + n0;
#pragma unroll
            for (int j = 0; j < 4; j++) {
                float xx = acc[i][j] + B1[e * FFNf + n0 + tn + j];
                g_hbuf[crow + tn + j] = 0.5f * xx * (1.0f + erff(xx * 0.70710678f));
            }
        }
    }
}

// ---------------------------------------------------------------------------
// Grouped FFN2: moe_out[token] += wt * (h @ W2[e]^T + b2[e])
// grid (Tt/64, D/64, E)
// ---------------------------------------------------------------------------
__global__ void ffn2_kernel(const float* __restrict__ W2, const float* __restrict__ B2) {
    int e = blockIdx.z;
    int cnt = g_cnt[e];
    int m0 = blockIdx.x * 64;
    if (m0 >= cnt) return;
    int n0 = blockIdx.y * 64;
    const float* W = W2 + (size_t)e * Dd * FFNf;

    __shared__ float As[16][64];
    __shared__ float Ws[16][64];
    int tid = threadIdx.x;
    int lr = tid >> 2, lc = (tid & 3) * 4;
    int tm = (tid >> 4) * 4, tn = (tid & 15) * 4;

    int r = m0 + lr;
    int tok2 = (r < cnt) ? g_tok[e * Tt + r] : -1;
    const float* Ap = (tok2 >= 0) ? (g_hbuf + (size_t)tok2 * FFNf + lc) : g_hbuf;
    const float* Wp = W + (size_t)(n0 + lr) * FFNf + lc;

    float acc[4][4] = {};
    for (int k0 = 0; k0 < FFNf; k0 += 16) {
        float4 a = (tok2 >= 0) ? *(const float4*)(Ap + k0) : make_float4(0, 0, 0, 0);
        float4 w = *(const float4*)(Wp + k0);
        As[lc+0][lr] = a.x; As[lc+1][lr] = a.y; As[lc+2][lr] = a.z; As[lc+3][lr] = a.w;
        Ws[lc+0][lr] = w.x; Ws[lc+1][lr] = w.y; Ws[lc+2][lr] = w.z; Ws[lc+3][lr] = w.w;
        __syncthreads();
#pragma unroll
        for (int kk = 0; kk < 16; kk++) {
            float4 av = *(const float4*)&As[kk][tm];
            float4 wv = *(const float4*)&Ws[kk][tn];
            acc[0][0] += av.x*wv.x; acc[0][1] += av.x*wv.y; acc[0][2] += av.x*wv.z; acc[0][3] += av.x*wv.w;
            acc[1][0] += av.y*wv.x; acc[1][1] += av.y*wv.y; acc[1][2] += av.y*wv.z; acc[1][3] += av.y*wv.w;
            acc[2][0] += av.z*wv.x; acc[2][1] += av.z*wv.y; acc[2][2] += av.z*wv.z; acc[2][3] += av.z*wv.w;
            acc[3][0] += av.w*wv.x; acc[3][1] += av.w*wv.y; acc[3][2] += av.w*wv.z; acc[3][3] += av.w*wv.w;
        }
        __syncthreads();
    }
#pragma unroll
    for (int i = 0; i < 4; i++) {
        int rr = m0 + tm + i;
        if (rr < cnt) {
            int t2 = g_tok[e * Tt + rr];
            float wt = g_wt[e * Tt + rr];
            size_t crow = (size_t)(t2 >> 1) * Dd + n0;
#pragma unroll
            for (int j = 0; j < 4; j++) {
                float val = acc[i][j] + B2[e * Dd + n0 + tn + j];
                atomicAdd(&g_moe[crow + tn + j], wt * val);
            }
        }
    }
}

// ---------------------------------------------------------------------------
// Launch
// ---------------------------------------------------------------------------
extern "C" void kernel_launch(void* const* d_in, const int* in_sizes, int n_in,
                              void* d_out, int out_size) {
    const float* hs    = (const float*)d_in[0];
    const float* q_w   = (const float*)d_in[1];
    const float* q_b   = (const float*)d_in[2];
    const float* k_w   = (const float*)d_in[3];
    const float* k_b   = (const float*)d_in[4];
    const float* v_w   = (const float*)d_in[5];
    const float* v_b   = (const float*)d_in[6];
    const float* o_w   = (const float*)d_in[7];
    const float* o_b   = (const float*)d_in[8];
    const float* ln1_g = (const float*)d_in[9];
    const float* ln1_b = (const float*)d_in[10];
    const float* gatew = (const float*)d_in[11];
    const float* e_w1  = (const float*)d_in[12];
    const float* e_b1  = (const float*)d_in[13];
    const float* e_w2  = (const float*)d_in[14];
    const float* e_b2  = (const float*)d_in[15];
    const float* ln2_g = (const float*)d_in[16];
    const float* ln2_b = (const float*)d_in[17];
    float* out = (float*)d_out;

    (void)in_sizes; (void)n_in;

    // 0) zero accumulators
    zero_kernel<<<(Tt * Dd) / 256, 256>>>();

    // 1) QKV projections
    dim3 ggrid(Tt / 64, Dd / 64);
    gemm_bias<<<ggrid, 256>>>(hs, 0, q_w, q_b, 0, Dd);
    gemm_bias<<<ggrid, 256>>>(hs, 0, k_w, k_b, 1, Dd);
    gemm_bias<<<ggrid, 256>>>(hs, 0, v_w, v_b, 2, Dd);

    // 2) partial RoPE on q, k
    rope_kernel<<<(Tt * Hh * 16 + 255) / 256, 256>>>();

    // 3) attention
    attn_kernel<<<dim3(Ss / 64, Hh, Bb), 64>>>();

    // 4) output projection
    gemm_bias<<<ggrid, 256>>>(nullptr, 1, o_w, o_b, 3, Dd);

    // 5) residual + LN1 -> g_h1
    add_ln<<<Tt, 128>>>(hs, ln1_g, ln1_b, nullptr, 0);

    // 6) router + lb loss
    router_kernel<<<Tt / 4, 128>>>(gatew);
    lb1_kernel<<<Ee, 256>>>();
    lb2_kernel<<<1, 1>>>(out + (out_size - 1));

    // 7) grouped MoE FFN (sparse top-2, exact vs dense reference)
    ffn1_kernel<<<dim3(Tt / 64, FFNf / 64, Ee), 256>>>(e_w1, e_b1);
    ffn2_kernel<<<dim3(Tt / 64, Dd / 64, Ee), 256>>>(e_w2, e_b2);

    // 8) residual + LN2 -> d_out
    add_ln<<<Tt, 128>>>(nullptr, ln2_g, ln2_b, out, 1);
}

// round 2
// speedup vs baseline: 1.4704x; 1.4704x over previous
#include <cuda_runtime.h>
#include <math.h>

// Problem constants
#define Bb   32
#define Ss   512
#define Dd   512
#define Hh   8
#define HDd  64
#define Ee   8
#define FFNf 2048
#define Tt   (Bb*Ss)     // 16384 tokens

// ---------------------------------------------------------------------------
// Scratch (device globals; no allocations allowed)
// ---------------------------------------------------------------------------
__device__ float g_q[Tt*Dd];
__device__ float g_k[Tt*Dd];
__device__ float g_v[Tt*Dd];
__device__ float g_attn[Tt*Dd];
__device__ float g_proj[Tt*Dd];
__device__ float g_h1[Tt*Dd];
__device__ float g_moe2[(size_t)Tt*2*Dd];    // per-slot FFN2 output (64 MB)
__device__ float g_router[Tt*Ee];
__device__ float g_hbuf[(size_t)Tt*2*FFNf];  // per-slot FFN1 hidden (268 MB)
__device__ int   g_cnt[Ee];
__device__ int   g_tok[Ee*Tt];
__device__ float g_wt[Ee*Tt];
__device__ float g_rsum[Ee];

// ---------------------------------------------------------------------------
__global__ void zero_cnt() {
    if (threadIdx.x < Ee) g_cnt[threadIdx.x] = 0;
}

// ---------------------------------------------------------------------------
// 128x128x8 double-buffered SGEMM: C = A * W^T + bias
// A [M,K] rowmajor, W [N,K] rowmajor. 256 threads, 8x8 per thread.
// asel: 0 -> A = Aext, 1 -> A = g_attn.   dsel: 0 q,1 k,2 v,3 proj. K=N=512.
// ---------------------------------------------------------------------------
__global__ void __launch_bounds__(256) gemm_bias2(const float* __restrict__ Aext, int asel,
                                                  const float* __restrict__ W,
                                                  const float* __restrict__ bias, int dsel) {
    const int K = 512, N = 512;
    const float* A = asel ? g_attn : Aext;
    float* C = (dsel == 0) ? g_q : (dsel == 1) ? g_k : (dsel == 2) ? g_v : g_proj;

    __shared__ __align__(16) float As[2][8][132];
    __shared__ __align__(16) float Bs[2][8][132];

    int tid = threadIdx.x;
    int m0 = blockIdx.x * 128, n0 = blockIdx.y * 128;
    int arow = tid >> 1, acol = (tid & 1) * 4;
    int ty = tid >> 4, tx = tid & 15;

    const float* Ap = A + (size_t)(m0 + arow) * K + acol;
    const float* Wp = W + (size_t)(n0 + arow) * K + acol;

    float4 ra = *(const float4*)Ap;
    float4 rb = *(const float4*)Wp;
    As[0][acol+0][arow] = ra.x; As[0][acol+1][arow] = ra.y; As[0][acol+2][arow] = ra.z; As[0][acol+3][arow] = ra.w;
    Bs[0][acol+0][arow] = rb.x; Bs[0][acol+1][arow] = rb.y; Bs[0][acol+2][arow] = rb.z; Bs[0][acol+3][arow] = rb.w;
    __syncthreads();

    float acc[8][8] = {};
    int buf = 0;
    const int NT = K / 8;
    for (int kt = 1; kt <= NT; kt++) {
        float4 na, nb;
        if (kt < NT) { na = *(const float4*)(Ap + kt * 8); nb = *(const float4*)(Wp + kt * 8); }
#pragma unroll
        for (int k = 0; k < 8; k++) {
            float4 a0 = *(const float4*)&As[buf][k][ty*4];
            float4 a1 = *(const float4*)&As[buf][k][ty*4+64];
            float4 b0 = *(const float4*)&Bs[buf][k][tx*4];
            float4 b1 = *(const float4*)&Bs[buf][k][tx*4+64];
            float am[8] = {a0.x,a0.y,a0.z,a0.w,a1.x,a1.y,a1.z,a1.w};
            float bn[8] = {b0.x,b0.y,b0.z,b0.w,b1.x,b1.y,b1.z,b1.w};
#pragma unroll
            for (int i = 0; i < 8; i++)
#pragma unroll
                for (int j = 0; j < 8; j++) acc[i][j] += am[i] * bn[j];
        }
        if (kt < NT) {
            int nb_ = buf ^ 1;
            As[nb_][acol+0][arow] = na.x; As[nb_][acol+1][arow] = na.y; As[nb_][acol+2][arow] = na.z; As[nb_][acol+3][arow] = na.w;
            Bs[nb_][acol+0][arow] = nb.x; Bs[nb_][acol+1][arow] = nb.y; Bs[nb_][acol+2][arow] = nb.z; Bs[nb_][acol+3][arow] = nb.w;
            __syncthreads();
            buf ^= 1;
        }
    }

#pragma unroll
    for (int i = 0; i < 8; i++) {
        int m = m0 + ty*4 + (i & 3) + (i >> 2) * 64;
        size_t base = (size_t)m * N + n0;
        float4 v0, v1;
        v0.x = acc[i][0] + bias[n0+tx*4+0]; v0.y = acc[i][1] + bias[n0+tx*4+1];
        v0.z = acc[i][2] + bias[n0+tx*4+2]; v0.w = acc[i][3] + bias[n0+tx*4+3];
        v1.x = acc[i][4] + bias[n0+tx*4+64]; v1.y = acc[i][5] + bias[n0+tx*4+65];
        v1.z = acc[i][6] + bias[n0+tx*4+66]; v1.w = acc[i][7] + bias[n0+tx*4+67];
        *(float4*)(C + base + tx*4)      = v0;
        *(float4*)(C + base + tx*4 + 64) = v1;
    }
}

// ---------------------------------------------------------------------------
// Partial RoPE (first 32 of each 64-dim head; half=16), applied to q and k.
// ---------------------------------------------------------------------------
__global__ void rope_kernel() {
    int idx = blockIdx.x * 256 + threadIdx.x;
    if (idx >= Tt * Hh * 16) return;
    int i = idx & 15;
    int h = (idx >> 4) & 7;
    int t = idx >> 7;
    int spos = t & (Ss - 1);
    float inv = powf(10000.0f, -(float)i * 2.0f / 32.0f);
    float ang = (float)spos * inv;
    float sn, cs;
    sincosf(ang, &sn, &cs);
    int base = t * Dd + h * 64;
    float x1 = g_q[base + i], x2 = g_q[base + 16 + i];
    g_q[base + i]      = x1 * cs - x2 * sn;
    g_q[base + 16 + i] = x2 * cs + x1 * sn;
    x1 = g_k[base + i]; x2 = g_k[base + 16 + i];
    g_k[base + i]      = x1 * cs - x2 * sn;
    g_k[base + 16 + i] = x2 * cs + x1 * sn;
}

// ---------------------------------------------------------------------------
// Flash attention: grid (S/64, H, B), 64 threads; each thread owns one q row.
// ---------------------------------------------------------------------------
__global__ void __launch_bounds__(64) attn_kernel() {
    __shared__ float Ks[32][64];
    __shared__ float Vs[32][64];

    int qt = blockIdx.x, h = blockIdx.y, b = blockIdx.z;
    int r = threadIdx.x;
    int srow = qt * 64 + r;
    const float* qp = g_q + (size_t)(b * Ss + srow) * Dd + h * 64;

    float q[64];
#pragma unroll
    for (int d = 0; d < 64; d++) q[d] = qp[d] * 0.125f;

    float o[64];
#pragma unroll
    for (int d = 0; d < 64; d++) o[d] = 0.0f;
    float m = -1e30f, l = 0.0f;

    for (int j0 = 0; j0 < Ss; j0 += 32) {
        for (int i = 0; i < 32; i++) {
            Ks[i][r] = g_k[(size_t)(b * Ss + j0 + i) * Dd + h * 64 + r];
            Vs[i][r] = g_v[(size_t)(b * Ss + j0 + i) * Dd + h * 64 + r];
        }
        __syncthreads();

        float s[32];
#pragma unroll
        for (int c = 0; c < 32; c++) {
            float acc = 0.0f;
#pragma unroll
            for (int d = 0; d < 64; d++) acc += q[d] * Ks[c][d];
            s[c] = acc;
        }
        float tmax = m;
#pragma unroll
        for (int c = 0; c < 32; c++) tmax = fmaxf(tmax, s[c]);
        float scale = __expf(m - tmax);
        l *= scale;
#pragma unroll
        for (int d = 0; d < 64; d++) o[d] *= scale;
        m = tmax;
#pragma unroll
        for (int c = 0; c < 32; c++) {
            float p = __expf(s[c] - m);
            l += p;
            s[c] = p;
        }
#pragma unroll
        for (int c = 0; c < 32; c++) {
            float p = s[c];
#pragma unroll
            for (int d = 0; d < 64; d++) o[d] += p * Vs[c][d];
        }
        __syncthreads();
    }
    float inv = 1.0f / l;
    float* op = g_attn + (size_t)(b * Ss + srow) * Dd + h * 64;
#pragma unroll
    for (int d = 0; d < 64; d++) op[d] = o[d] * inv;
}

// ---------------------------------------------------------------------------
// out = LayerNorm(x + y) ; mode 0: x=hs, y=g_proj, out=g_h1
//                          mode 1: x=g_h1, y=g_moe2[2t]+g_moe2[2t+1], out=d_out
// ---------------------------------------------------------------------------
__global__ void add_ln(const float* __restrict__ xe,
                       const float* __restrict__ g, const float* __restrict__ bb,
                       float* __restrict__ oe, int mode) {
    int row = blockIdx.x, tid = threadIdx.x;   // 128 threads
    size_t base = (size_t)row * Dd;
    float v[4]; float s = 0.0f, sq = 0.0f;
#pragma unroll
    for (int i = 0; i < 4; i++) {
        int c = tid + i * 128;
        float t;
        if (mode == 0) t = xe[base + c] + g_proj[base + c];
        else           t = g_h1[base + c] + (g_moe2[(size_t)(2*row) * Dd + c] + g_moe2[(size_t)(2*row+1) * Dd + c]);
        v[i] = t; s += t; sq += t * t;
    }
#pragma unroll
    for (int off = 16; off; off >>= 1) {
        s  += __shfl_down_sync(0xffffffffu, s,  off);
        sq += __shfl_down_sync(0xffffffffu, sq, off);
    }
    __shared__ float rs[4], rq[4];
    int warp = tid >> 5, lane = tid & 31;
    if (lane == 0) { rs[warp] = s; rq[warp] = sq; }
    __syncthreads();
    if (tid == 0) {
        float S = rs[0] + rs[1] + rs[2] + rs[3];
        float Q = rq[0] + rq[1] + rq[2] + rq[3];
        rs[0] = S; rq[0] = Q;
    }
    __syncthreads();
    float mean = rs[0] * (1.0f / Dd);
    float var  = rq[0] * (1.0f / Dd) - mean * mean;
    float rstd = rsqrtf(var + 1e-5f);
    float* o = (mode == 0) ? g_h1 : oe;
#pragma unroll
    for (int i = 0; i < 4; i++) {
        int c = tid + i * 128;
        o[base + c] = (v[i] - mean) * rstd * g[c] + bb[c];
    }
}

// ---------------------------------------------------------------------------
// Router: one warp per token.
// ---------------------------------------------------------------------------
__global__ void router_kernel(const float* __restrict__ gw) {
    int warp = threadIdx.x >> 5, lane = threadIdx.x & 31;
    int t = blockIdx.x * 4 + warp;
    const float* x = g_h1 + (size_t)t * Dd;
    float acc[8] = {};
    for (int d = lane; d < Dd; d += 32) {
        float xv = x[d];
#pragma unroll
        for (int e = 0; e < 8; e++) acc[e] += xv * gw[e * Dd + d];
    }
#pragma unroll
    for (int e = 0; e < 8; e++)
#pragma unroll
        for (int off = 16; off; off >>= 1)
            acc[e] += __shfl_xor_sync(0xffffffffu, acc[e], off);

    if (lane == 0) {
        float mx = acc[0];
#pragma unroll
        for (int e = 1; e < 8; e++) mx = fmaxf(mx, acc[e]);
        float p[8], sm = 0.0f;
#pragma unroll
        for (int e = 0; e < 8; e++) { p[e] = __expf(acc[e] - mx); sm += p[e]; }
        float inv = 1.0f / sm;
#pragma unroll
        for (int e = 0; e < 8; e++) { p[e] *= inv; g_router[t * 8 + e] = p[e]; }
        int i1 = 0;
#pragma unroll
        for (int e = 1; e < 8; e++) if (p[e] > p[i1]) i1 = e;
        int i2 = (i1 == 0) ? 1 : 0;
#pragma unroll
        for (int e = 0; e < 8; e++) if (e != i1 && p[e] > p[i2]) i2 = e;
        float wsum = p[i1] + p[i2];
        int s1 = atomicAdd(&g_cnt[i1], 1);
        g_tok[i1 * Tt + s1] = t * 2;     g_wt[i1 * Tt + s1] = p[i1] / wsum;
        int s2 = atomicAdd(&g_cnt[i2], 1);
        g_tok[i2 * Tt + s2] = t * 2 + 1; g_wt[i2 * Tt + s2] = p[i2] / wsum;
    }
}

__global__ void lb1_kernel() {
    int e = blockIdx.x;
    float p = 0.0f;
    for (int t = threadIdx.x; t < Tt; t += 256) p += g_router[t * 8 + e];
    __shared__ float sm[256];
    sm[threadIdx.x] = p; __syncthreads();
    for (int s = 128; s; s >>= 1) {
        if (threadIdx.x < s) sm[threadIdx.x] += sm[threadIdx.x + s];
        __syncthreads();
    }
    if (threadIdx.x == 0) g_rsum[e] = sm[0];
}
__global__ void lb2_kernel(float* __restrict__ dst) {
    float acc = 0.0f;
#pragma unroll
    for (int e = 0; e < 8; e++) { float m = g_rsum[e] * (1.0f / Tt); acc += m * m; }
    *dst = 8.0f * acc;
}

// ---------------------------------------------------------------------------
// FFN1 (gathered): h = gelu(x_tok @ W1[e]^T + b1[e]) -> g_hbuf[slot]
// 128x128x8 double-buffered. grid (Tt/128, FFN/128, E), early exit.
// ---------------------------------------------------------------------------
__global__ void __launch_bounds__(256) ffn1_kernel(const float* __restrict__ W1, const float* __restrict__ B1) {
    int e = blockIdx.z;
    int cnt = g_cnt[e];
    int m0 = blockIdx.x * 128;
    if (m0 >= cnt) return;
    int n0 = blockIdx.y * 128;
    const int K = Dd;
    const float* W = W1 + (size_t)e * FFNf * Dd;

    __shared__ __align__(16) float As[2][8][132];
    __shared__ __align__(16) float Bs[2][8][132];

    int tid = threadIdx.x;
    int arow = tid >> 1, acol = (tid & 1) * 4;
    int ty = tid >> 4, tx = tid & 15;

    int r = m0 + arow;
    int slot = (r < cnt) ? g_tok[e * Tt + r] : 0;
    const float* Ap = g_h1 + (size_t)(slot >> 1) * Dd + acol;
    const float* Wp = W + (size_t)(n0 + arow) * K + acol;

    float4 ra = *(const float4*)Ap;
    float4 rb = *(const float4*)Wp;
    As[0][acol+0][arow] = ra.x; As[0][acol+1][arow] = ra.y; As[0][acol+2][arow] = ra.z; As[0][acol+3][arow] = ra.w;
    Bs[0][acol+0][arow] = rb.x; Bs[0][acol+1][arow] = rb.y; Bs[0][acol+2][arow] = rb.z; Bs[0][acol+3][arow] = rb.w;
    __syncthreads();

    float acc[8][8] = {};
    int buf = 0;
    const int NT = K / 8;
    for (int kt = 1; kt <= NT; kt++) {
        float4 na, nb;
        if (kt < NT) { na = *(const float4*)(Ap + kt * 8); nb = *(const float4*)(Wp + kt * 8); }
#pragma unroll
        for (int k = 0; k < 8; k++) {
            float4 a0 = *(const float4*)&As[buf][k][ty*4];
            float4 a1 = *(const float4*)&As[buf][k][ty*4+64];
            float4 b0 = *(const float4*)&Bs[buf][k][tx*4];
            float4 b1 = *(const float4*)&Bs[buf][k][tx*4+64];
            float am[8] = {a0.x,a0.y,a0.z,a0.w,a1.x,a1.y,a1.z,a1.w};
            float bn[8] = {b0.x,b0.y,b0.z,b0.w,b1.x,b1.y,b1.z,b1.w};
#pragma unroll
            for (int i = 0; i < 8; i++)
#pragma unroll
                for (int j = 0; j < 8; j++) acc[i][j] += am[i] * bn[j];
        }
        if (kt < NT) {
            int nb_ = buf ^ 1;
            As[nb_][acol+0][arow] = na.x; As[nb_][acol+1][arow] = na.y; As[nb_][acol+2][arow] = na.z; As[nb_][acol+3][arow] = na.w;
            Bs[nb_][acol+0][arow] = nb.x; Bs[nb_][acol+1][arow] = nb.y; Bs[nb_][acol+2][arow] = nb.z; Bs[nb_][acol+3][arow] = nb.w;
            __syncthreads();
            buf ^= 1;
        }
    }

#pragma unroll
    for (int i = 0; i < 8; i++) {
        int rr = m0 + ty*4 + (i & 3) + (i >> 2) * 64;
        if (rr < cnt) {
            int s2 = g_tok[e * Tt + rr];
            size_t base = (size_t)s2 * FFNf + n0;
#pragma unroll
            for (int j = 0; j < 8; j++) {
                int c = tx*4 + (j & 3) + (j >> 2) * 64;
                float xx = acc[i][j] + B1[e * FFNf + n0 + c];
                g_hbuf[base + c] = 0.5f * xx * (1.0f + erff(xx * 0.70710678f));
            }
        }
    }
}

// ---------------------------------------------------------------------------
// FFN2 (gathered): g_moe2[slot] = wt * (h_slot @ W2[e]^T + b2[e])
// grid (Tt/128, D/128, E)
// ---------------------------------------------------------------------------
__global__ void __launch_bounds__(256) ffn2_kernel(const float* __restrict__ W2, const float* __restrict__ B2) {
    int e = blockIdx.z;
    int cnt = g_cnt[e];
    int m0 = blockIdx.x * 128;
    if (m0 >= cnt) return;
    int n0 = blockIdx.y * 128;
    const int K = FFNf;
    const float* W = W2 + (size_t)e * Dd * FFNf;

    __shared__ __align__(16) float As[2][8][132];
    __shared__ __align__(16) float Bs[2][8][132];

    int tid = threadIdx.x;
    int arow = tid >> 1, acol = (tid & 1) * 4;
    int ty = tid >> 4, tx = tid & 15;

    int r = m0 + arow;
    int slot = (r < cnt) ? g_tok[e * Tt + r] : 0;
    const float* Ap = g_hbuf + (size_t)slot * FFNf + acol;
    const float* Wp = W + (size_t)(n0 + arow) * K + acol;

    float4 ra = *(const float4*)Ap;
    float4 rb = *(const float4*)Wp;
    As[0][acol+0][arow] = ra.x; As[0][acol+1][arow] = ra.y; As[0][acol+2][arow] = ra.z; As[0][acol+3][arow] = ra.w;
    Bs[0][acol+0][arow] = rb.x; Bs[0][acol+1][arow] = rb.y; Bs[0][acol+2][arow] = rb.z; Bs[0][acol+3][arow] = rb.w;
    __syncthreads();

    float acc[8][8] = {};
    int buf = 0;
    const int NT = K / 8;
    for (int kt = 1; kt <= NT; kt++) {
        float4 na, nb;
        if (kt < NT) { na = *(const float4*)(Ap + kt * 8); nb = *(const float4*)(Wp + kt * 8); }
#pragma unroll
        for (int k = 0; k < 8; k++) {
            float4 a0 = *(const float4*)&As[buf][k][ty*4];
            float4 a1 = *(const float4*)&As[buf][k][ty*4+64];
            float4 b0 = *(const float4*)&Bs[buf][k][tx*4];
            float4 b1 = *(const float4*)&Bs[buf][k][tx*4+64];
            float am[8] = {a0.x,a0.y,a0.z,a0.w,a1.x,a1.y,a1.z,a1.w};
            float bn[8] = {b0.x,b0.y,b0.z,b0.w,b1.x,b1.y,b1.z,b1.w};
#pragma unroll
            for (int i = 0; i < 8; i++)
#pragma unroll
                for (int j = 0; j < 8; j++) acc[i][j] += am[i] * bn[j];
        }
        if (kt < NT) {
            int nb_ = buf ^ 1;
            As[nb_][acol+0][arow] = na.x; As[nb_][acol+1][arow] = na.y; As[nb_][acol+2][arow] = na.z; As[nb_][acol+3][arow] = na.w;
            Bs[nb_][acol+0][arow] = nb.x; Bs[nb_][acol+1][arow] = nb.y; Bs[nb_][acol+2][arow] = nb.z; Bs[nb_][acol+3][arow] = nb.w;
            __syncthreads();
            buf ^= 1;
        }
    }

#pragma unroll
    for (int i = 0; i < 8; i++) {
        int rr = m0 + ty*4 + (i & 3) + (i >> 2) * 64;
        if (rr < cnt) {
            int s2 = g_tok[e * Tt + rr];
            float wt = g_wt[e * Tt + rr];
            size_t base = (size_t)s2 * Dd + n0;
#pragma unroll
            for (int j = 0; j < 8; j++) {
                int c = tx*4 + (j & 3) + (j >> 2) * 64;
                g_moe2[base + c] = wt * (acc[i][j] + B2[e * Dd + n0 + c]);
            }
        }
    }
}

// ---------------------------------------------------------------------------
// Launch
// ---------------------------------------------------------------------------
extern "C" void kernel_launch(void* const* d_in, const int* in_sizes, int n_in,
                              void* d_out, int out_size) {
    const float* hs    = (const float*)d_in[0];
    const float* q_w   = (const float*)d_in[1];
    const float* q_b   = (const float*)d_in[2];
    const float* k_w   = (const float*)d_in[3];
    const float* k_b   = (const float*)d_in[4];
    const float* v_w   = (const float*)d_in[5];
    const float* v_b   = (const float*)d_in[6];
    const float* o_w   = (const float*)d_in[7];
    const float* o_b   = (const float*)d_in[8];
    const float* ln1_g = (const float*)d_in[9];
    const float* ln1_b = (const float*)d_in[10];
    const float* gatew = (const float*)d_in[11];
    const float* e_w1  = (const float*)d_in[12];
    const float* e_b1  = (const float*)d_in[13];
    const float* e_w2  = (const float*)d_in[14];
    const float* e_b2  = (const float*)d_in[15];
    const float* ln2_g = (const float*)d_in[16];
    const float* ln2_b = (const float*)d_in[17];
    float* out = (float*)d_out;

    (void)in_sizes; (void)n_in;

    zero_cnt<<<1, 32>>>();

    // QKV projections
    dim3 ggrid(Tt / 128, Dd / 128);
    gemm_bias2<<<ggrid, 256>>>(hs, 0, q_w, q_b, 0);
    gemm_bias2<<<ggrid, 256>>>(hs, 0, k_w, k_b, 1);
    gemm_bias2<<<ggrid, 256>>>(hs, 0, v_w, v_b, 2);

    rope_kernel<<<(Tt * Hh * 16 + 255) / 256, 256>>>();

    attn_kernel<<<dim3(Ss / 64, Hh, Bb), 64>>>();

    gemm_bias2<<<ggrid, 256>>>(nullptr, 1, o_w, o_b, 3);

    add_ln<<<Tt, 128>>>(hs, ln1_g, ln1_b, nullptr, 0);

    router_kernel<<<Tt / 4, 128>>>(gatew);
    lb1_kernel<<<Ee, 256>>>();
    lb2_kernel<<<1, 1>>>(out + (out_size - 1));

    ffn1_kernel<<<dim3(Tt / 128, FFNf / 128, Ee), 256>>>(e_w1, e_b1);
    ffn2_kernel<<<dim3(Tt / 128, Dd / 128, Ee), 256>>>(e_w2, e_b2);

    add_ln<<<Tt, 128>>>(nullptr, ln2_g, ln2_b, out, 1);
}

// round 4
// speedup vs baseline: 4.2756x; 2.9078x over previous
#include <cuda_runtime.h>
#include <cuda_fp16.h>
#include <math.h>
#include <stdint.h>

// Problem constants
#define Bb   32
#define Ss   512
#define Dd   512
#define Hh   8
#define Ee   8
#define FFNf 2048
#define Tt   (Bb*Ss)     // 16384 tokens

// ===========================================================================
// Scratch (device globals; no allocations allowed)
// ===========================================================================
__device__ float g_q[Tt*Dd];
__device__ float g_k[Tt*Dd];
__device__ float g_v[Tt*Dd];
__device__ float g_attn[Tt*Dd];
__device__ float g_proj[Tt*Dd];
__device__ float g_h1[Tt*Dd];
__device__ float g_moe2[(size_t)Tt*2*Dd];
__device__ float g_router[Tt*Ee];
__device__ int   g_cnt[Ee];
__device__ int   g_tok[Ee*Tt];
__device__ float g_wt[Ee*Tt];
__device__ float g_rsum[Ee];

// fp16 buffers
__device__ __half g_hsh [Tt*Dd];
__device__ __half g_atth[Tt*Dd];
__device__ __half g_h1h [Tt*Dd];
__device__ __half g_wqh [Dd*Dd];
__device__ __half g_wkh [Dd*Dd];
__device__ __half g_wvh [Dd*Dd];
__device__ __half g_woh [Dd*Dd];
__device__ __half g_w1h [(size_t)Ee*FFNf*Dd];
__device__ __half g_w2h [(size_t)Ee*Dd*FFNf];
__device__ __half g_hbufh[(size_t)Tt*2*FFNf];   // per-slot gelu hidden (fp16)

// ===========================================================================
__global__ void zero_cnt() { if (threadIdx.x < Ee) g_cnt[threadIdx.x] = 0; }

// fp32 -> fp16 (vectorized, tot must be multiple of 4)
__global__ void conv16(const float* __restrict__ s, __half* __restrict__ d, int tot4) {
    int i = blockIdx.x * 256 + threadIdx.x;
    if (i >= tot4) return;
    float4 v = ((const float4*)s)[i];
    ((__half2*)d)[2*i]   = __floats2half2_rn(v.x, v.y);
    ((__half2*)d)[2*i+1] = __floats2half2_rn(v.z, v.w);
}

// ===========================================================================
// HMMA helpers (sm_80+ baseline; compiles at compute_103)
// ===========================================================================
__device__ __forceinline__ uint32_t smem_to_u32(const void* p) {
    uint32_t a;
    asm("{ .reg .u64 t; cvta.to.shared.u64 t, %1; cvt.u32.u64 %0, t; }" : "=r"(a) : "l"(p));
    return a;
}
__device__ __forceinline__ void ldsm_x4(uint32_t& r0, uint32_t& r1, uint32_t& r2, uint32_t& r3, uint32_t a) {
    asm volatile("ldmatrix.sync.aligned.m8n8.x4.shared.b16 {%0,%1,%2,%3}, [%4];"
        : "=r"(r0), "=r"(r1), "=r"(r2), "=r"(r3) : "r"(a));
}
__device__ __forceinline__ void ldsm_x2(uint32_t& r0, uint32_t& r1, uint32_t a) {
    asm volatile("ldmatrix.sync.aligned.m8n8.x2.shared.b16 {%0,%1}, [%2];"
        : "=r"(r0), "=r"(r1) : "r"(a));
}
__device__ __forceinline__ void mma16816(float* c, uint32_t a0, uint32_t a1, uint32_t a2, uint32_t a3,
                                         uint32_t b0, uint32_t b1) {
    asm volatile("mma.sync.aligned.m16n8k16.row.col.f32.f16.f16.f32 "
        "{%0,%1,%2,%3}, {%4,%5,%6,%7}, {%8,%9}, {%0,%1,%2,%3};"
        : "+f"(c[0]), "+f"(c[1]), "+f"(c[2]), "+f"(c[3])
        : "r"(a0), "r"(a1), "r"(a2), "r"(a3), "r"(b0), "r"(b1));
}
#define CP_ASYNC16(dst, src) \
    asm volatile("cp.async.cg.shared.global [%0], [%1], 16;" :: "r"(dst), "l"(src))
#define CP_COMMIT() asm volatile("cp.async.commit_group;" ::: "memory")
#define CP_WAIT0()  asm volatile("cp.async.wait_group 0;" ::: "memory")

// ===========================================================================
// fp16 HMMA GEMM: C = A @ W^T (+bias, +activation), 128x128 tile, k64 chunks,
// cp.async double buffer, SW128 swizzle, ldmatrix fragments.
// MODE 0: proj  (A rows identity, out fp32 Cf)
// MODE 1: ffn1  (gathered tokens, out gelu -> g_hbufh fp16)
// MODE 2: ffn2  (gathered slots,  out wt*(.) -> g_moe2 fp32)
// ===========================================================================
#define SMEM_BYTES (2048 + 2*32768)

template<int MODE>
__global__ void __launch_bounds__(256) hgemm(const __half* __restrict__ A,
                                             const __half* __restrict__ Bw,
                                             const float* __restrict__ bias,
                                             float* __restrict__ Cf) {
    constexpr int K  = (MODE == 2) ? FFNf : Dd;
    constexpr int NC = K / 64;
    constexpr int NW = (MODE == 1) ? FFNf : Dd;

    extern __shared__ char smem[];
    uint32_t sb = smem_to_u32(smem);
    int tid = threadIdx.x, wid = tid >> 5, lane = tid & 31;

    int e   = (MODE == 0) ? 0 : blockIdx.z;
    int cnt = (MODE == 0) ? Tt : g_cnt[e];
    int m0  = blockIdx.x * 128;
    if (m0 >= cnt) return;
    int n0  = blockIdx.y * 128;

    const __half* Wp = Bw + (size_t)e * NW * K;
    const float*  bp = bias + (size_t)e * NW;

    int*   s_row  = (int*)(smem);
    int*   s_slot = (int*)(smem + 512);
    float* s_wt   = (float*)(smem + 1024);
    if (tid < 128) {
        int r = m0 + tid;
        if (MODE == 0) { s_row[tid] = r; s_slot[tid] = r; }
        else {
            if (r < cnt) {
                int sl = g_tok[e * Tt + r];
                s_slot[tid] = sl;
                s_row[tid]  = (MODE == 1) ? (sl >> 1) : sl;
                if (MODE == 2) s_wt[tid] = g_wt[e * Tt + r];
            } else { s_slot[tid] = -1; s_row[tid] = 0; if (MODE == 2) s_wt[tid] = 0.f; }
        }
    }
    __syncthreads();

    // ---- async tile loader: chunk c -> buffer b (A 16KB + B 16KB) ----
    auto LOAD = [&](int c, int b) {
        int cbase = c * 64;
        uint32_t dstA = sb + 2048 + b * 32768;
        uint32_t dstB = dstA + 16384;
#pragma unroll
        for (int i = 0; i < 4; i++) {
            int u = tid + i * 256;
            int r = u >> 3, c16 = u & 7;
            uint32_t off = (uint32_t)(r * 128 + ((c16 * 16) ^ ((r & 7) << 4)));
            const __half* ga = A + (size_t)s_row[r] * K + cbase + c16 * 8;
            CP_ASYNC16(dstA + off, ga);
            const __half* gb = Wp + (size_t)(n0 + r) * K + cbase + c16 * 8;
            CP_ASYNC16(dstB + off, gb);
        }
        CP_COMMIT();
    };

    LOAD(0, 0);
    CP_WAIT0();
    __syncthreads();

    float acc[4][4][4];
#pragma unroll
    for (int a = 0; a < 4; a++)
#pragma unroll
        for (int b = 0; b < 4; b++)
#pragma unroll
            for (int c = 0; c < 4; c++) acc[a][b][c] = 0.f;

    int wm = (wid & 1) * 64, wn = (wid >> 1) * 32;
    uint32_t swz = (uint32_t)((lane & 7) << 4);
    int arow = wm + (lane & 7) + ((lane >> 3) & 1) * 8;   // + mt*16
    uint32_t acolsel = ((lane >> 4) & 1) * 16;
    int brow = wn + (lane & 7);                            // + nt*8
    uint32_t bcolsel = ((lane >> 3) & 1) * 16;

    for (int c = 0; c < NC; c++) {
        if (c + 1 < NC) LOAD(c + 1, (c + 1) & 1);
        uint32_t sA = sb + 2048 + (c & 1) * 32768;
        uint32_t sB = sA + 16384;
#pragma unroll
        for (int kk = 0; kk < 4; kk++) {
            uint32_t kb = (uint32_t)(kk * 32);
            uint32_t b0[4], b1[4];
#pragma unroll
            for (int nt = 0; nt < 4; nt++) {
                int r = brow + nt * 8;
                uint32_t addr = sB + r * 128 + ((kb + bcolsel) ^ swz);
                ldsm_x2(b0[nt], b1[nt], addr);
            }
#pragma unroll
            for (int mt = 0; mt < 4; mt++) {
                int r = arow + mt * 16;
                uint32_t addr = sA + r * 128 + ((kb + acolsel) ^ swz);
                uint32_t a0, a1, a2, a3;
                ldsm_x4(a0, a1, a2, a3, addr);
#pragma unroll
                for (int nt = 0; nt < 4; nt++)
                    mma16816(acc[mt][nt], a0, a1, a2, a3, b0[nt], b1[nt]);
            }
        }
        if (c + 1 < NC) CP_WAIT0();
        __syncthreads();
    }

    // ---- epilogue straight from registers ----
    int t4 = lane >> 2, tq = lane & 3;
#pragma unroll
    for (int mt = 0; mt < 4; mt++) {
        int rl0 = wm + mt * 16 + t4;
#pragma unroll
        for (int rr = 0; rr < 2; rr++) {
            int rl = rl0 + rr * 8;
            int slot = s_slot[rl];
            if (slot < 0) continue;
#pragma unroll
            for (int nt = 0; nt < 4; nt++) {
                int gc = n0 + wn + nt * 8 + tq * 2;
                float c0 = acc[mt][nt][rr * 2 + 0];
                float c1 = acc[mt][nt][rr * 2 + 1];
                if (MODE == 0) {
                    float2 o = make_float2(c0 + bp[gc], c1 + bp[gc + 1]);
                    *(float2*)(Cf + (size_t)slot * Dd + gc) = o;
                } else if (MODE == 1) {
                    float x0 = c0 + bp[gc], x1 = c1 + bp[gc + 1];
                    float g0 = 0.5f * x0 * (1.0f + erff(x0 * 0.70710678f));
                    float g1 = 0.5f * x1 * (1.0f + erff(x1 * 0.70710678f));
                    *(__half2*)(g_hbufh + (size_t)slot * FFNf + gc) = __floats2half2_rn(g0, g1);
                } else {
                    float wt = s_wt[rl];
                    float2 o = make_float2(wt * (c0 + bp[gc]), wt * (c1 + bp[gc + 1]));
                    *(float2*)(g_moe2 + (size_t)slot * Dd + gc) = o;
                }
            }
        }
    }
}

// ===========================================================================
// Partial RoPE (fp32, unchanged)
// ===========================================================================
__global__ void rope_kernel() {
    int idx = blockIdx.x * 256 + threadIdx.x;
    if (idx >= Tt * Hh * 16) return;
    int i = idx & 15;
    int h = (idx >> 4) & 7;
    int t = idx >> 7;
    int spos = t & (Ss - 1);
    float inv = powf(10000.0f, -(float)i * 2.0f / 32.0f);
    float ang = (float)spos * inv;
    float sn, cs;
    sincosf(ang, &sn, &cs);
    int base = t * Dd + h * 64;
    float x1 = g_q[base + i], x2 = g_q[base + 16 + i];
    g_q[base + i]      = x1 * cs - x2 * sn;
    g_q[base + 16 + i] = x2 * cs + x1 * sn;
    x1 = g_k[base + i]; x2 = g_k[base + 16 + i];
    g_k[base + i]      = x1 * cs - x2 * sn;
    g_k[base + 16 + i] = x2 * cs + x1 * sn;
}

// ===========================================================================
// Flash attention (fp32, unchanged)
// ===========================================================================
__global__ void __launch_bounds__(64) attn_kernel() {
    __shared__ float Ks[32][64];
    __shared__ float Vs[32][64];

    int qt = blockIdx.x, h = blockIdx.y, b = blockIdx.z;
    int r = threadIdx.x;
    int srow = qt * 64 + r;
    const float* qp = g_q + (size_t)(b * Ss + srow) * Dd + h * 64;

    float q[64];
#pragma unroll
    for (int d = 0; d < 64; d++) q[d] = qp[d] * 0.125f;

    float o[64];
#pragma unroll
    for (int d = 0; d < 64; d++) o[d] = 0.0f;
    float m = -1e30f, l = 0.0f;

    for (int j0 = 0; j0 < Ss; j0 += 32) {
        for (int i = 0; i < 32; i++) {
            Ks[i][r] = g_k[(size_t)(b * Ss + j0 + i) * Dd + h * 64 + r];
            Vs[i][r] = g_v[(size_t)(b * Ss + j0 + i) * Dd + h * 64 + r];
        }
        __syncthreads();

        float s[32];
#pragma unroll
        for (int c = 0; c < 32; c++) {
            float acc = 0.0f;
#pragma unroll
            for (int d = 0; d < 64; d++) acc += q[d] * Ks[c][d];
            s[c] = acc;
        }
        float tmax = m;
#pragma unroll
        for (int c = 0; c < 32; c++) tmax = fmaxf(tmax, s[c]);
        float scale = __expf(m - tmax);
        l *= scale;
#pragma unroll
        for (int d = 0; d < 64; d++) o[d] *= scale;
        m = tmax;
#pragma unroll
        for (int c = 0; c < 32; c++) {
            float p = __expf(s[c] - m);
            l += p;
            s[c] = p;
        }
#pragma unroll
        for (int c = 0; c < 32; c++) {
            float p = s[c];
#pragma unroll
            for (int d = 0; d < 64; d++) o[d] += p * Vs[c][d];
        }
        __syncthreads();
    }
    float inv = 1.0f / l;
    float* op = g_attn + (size_t)(b * Ss + srow) * Dd + h * 64;
#pragma unroll
    for (int d = 0; d < 64; d++) op[d] = o[d] * inv;
}

// ===========================================================================
// Residual + LayerNorm (fp32, unchanged)
// ===========================================================================
__global__ void add_ln(const float* __restrict__ xe,
                       const float* __restrict__ g, const float* __restrict__ bb,
                       float* __restrict__ oe, int mode) {
    int row = blockIdx.x, tid = threadIdx.x;
    size_t base = (size_t)row * Dd;
    float v[4]; float s = 0.0f, sq = 0.0f;
#pragma unroll
    for (int i = 0; i < 4; i++) {
        int c = tid + i * 128;
        float t;
        if (mode == 0) t = xe[base + c] + g_proj[base + c];
        else           t = g_h1[base + c] + (g_moe2[(size_t)(2*row) * Dd + c] + g_moe2[(size_t)(2*row+1) * Dd + c]);
        v[i] = t; s += t; sq += t * t;
    }
#pragma unroll
    for (int off = 16; off; off >>= 1) {
        s  += __shfl_down_sync(0xffffffffu, s,  off);
        sq += __shfl_down_sync(0xffffffffu, sq, off);
    }
    __shared__ float rs[4], rq[4];
    int warp = tid >> 5, lane = tid & 31;
    if (lane == 0) { rs[warp] = s; rq[warp] = sq; }
    __syncthreads();
    if (tid == 0) {
        float S = rs[0] + rs[1] + rs[2] + rs[3];
        float Q = rq[0] + rq[1] + rq[2] + rq[3];
        rs[0] = S; rq[0] = Q;
    }
    __syncthreads();
    float mean = rs[0] * (1.0f / Dd);
    float var  = rq[0] * (1.0f / Dd) - mean * mean;
    float rstd = rsqrtf(var + 1e-5f);
    float* o = (mode == 0) ? g_h1 : oe;
#pragma unroll
    for (int i = 0; i < 4; i++) {
        int c = tid + i * 128;
        o[base + c] = (v[i] - mean) * rstd * g[c] + bb[c];
    }
}

// ===========================================================================
// Router + lb loss (fp32, unchanged)
// ===========================================================================
__global__ void router_kernel(const float* __restrict__ gw) {
    int warp = threadIdx.x >> 5, lane = threadIdx.x & 31;
    int t = blockIdx.x * 4 + warp;
    const float* x = g_h1 + (size_t)t * Dd;
    float acc[8] = {};
    for (int d = lane; d < Dd; d += 32) {
        float xv = x[d];
#pragma unroll
        for (int e = 0; e < 8; e++) acc[e] += xv * gw[e * Dd + d];
    }
#pragma unroll
    for (int e = 0; e < 8; e++)
#pragma unroll
        for (int off = 16; off; off >>= 1)
            acc[e] += __shfl_xor_sync(0xffffffffu, acc[e], off);

    if (lane == 0) {
        float mx = acc[0];
#pragma unroll
        for (int e = 1; e < 8; e++) mx = fmaxf(mx, acc[e]);
        float p[8], sm = 0.0f;
#pragma unroll
        for (int e = 0; e < 8; e++) { p[e] = __expf(acc[e] - mx); sm += p[e]; }
        float inv = 1.0f / sm;
#pragma unroll
        for (int e = 0; e < 8; e++) { p[e] *= inv; g_router[t * 8 + e] = p[e]; }
        int i1 = 0;
#pragma unroll
        for (int e = 1; e < 8; e++) if (p[e] > p[i1]) i1 = e;
        int i2 = (i1 == 0) ? 1 : 0;
#pragma unroll
        for (int e = 0; e < 8; e++) if (e != i1 && p[e] > p[i2]) i2 = e;
        float wsum = p[i1] + p[i2];
        int s1 = atomicAdd(&g_cnt[i1], 1);
        g_tok[i1 * Tt + s1] = t * 2;     g_wt[i1 * Tt + s1] = p[i1] / wsum;
        int s2 = atomicAdd(&g_cnt[i2], 1);
        g_tok[i2 * Tt + s2] = t * 2 + 1; g_wt[i2 * Tt + s2] = p[i2] / wsum;
    }
}

__global__ void lb1_kernel() {
    int e = blockIdx.x;
    float p = 0.0f;
    for (int t = threadIdx.x; t < Tt; t += 256) p += g_router[t * 8 + e];
    __shared__ float sm[256];
    sm[threadIdx.x] = p; __syncthreads();
    for (int s = 128; s; s >>= 1) {
        if (threadIdx.x < s) sm[threadIdx.x] += sm[threadIdx.x + s];
        __syncthreads();
    }
    if (threadIdx.x == 0) g_rsum[e] = sm[0];
}
__global__ void lb2_kernel(float* __restrict__ dst) {
    float acc = 0.0f;
#pragma unroll
    for (int e = 0; e < 8; e++) { float m = g_rsum[e] * (1.0f / Tt); acc += m * m; }
    *dst = 8.0f * acc;
}

// ===========================================================================
// Launch
// ===========================================================================
extern "C" void kernel_launch(void* const* d_in, const int* in_sizes, int n_in,
                              void* d_out, int out_size) {
    const float* hs    = (const float*)d_in[0];
    const float* q_w   = (const float*)d_in[1];
    const float* q_b   = (const float*)d_in[2];
    const float* k_w   = (const float*)d_in[3];
    const float* k_b   = (const float*)d_in[4];
    const float* v_w   = (const float*)d_in[5];
    const float* v_b   = (const float*)d_in[6];
    const float* o_w   = (const float*)d_in[7];
    const float* o_b   = (const float*)d_in[8];
    const float* ln1_g = (const float*)d_in[9];
    const float* ln1_b = (const float*)d_in[10];
    const float* gatew = (const float*)d_in[11];
    const float* e_w1  = (const float*)d_in[12];
    const float* e_b1  = (const float*)d_in[13];
    const float* e_w2  = (const float*)d_in[14];
    const float* e_b2  = (const float*)d_in[15];
    const float* ln2_g = (const float*)d_in[16];
    const float* ln2_b = (const float*)d_in[17];
    float* out = (float*)d_out;

    (void)in_sizes; (void)n_in;

    cudaFuncSetAttribute(hgemm<0>, cudaFuncAttributeMaxDynamicSharedMemorySize, SMEM_BYTES);
    cudaFuncSetAttribute(hgemm<1>, cudaFuncAttributeMaxDynamicSharedMemorySize, SMEM_BYTES);
    cudaFuncSetAttribute(hgemm<2>, cudaFuncAttributeMaxDynamicSharedMemorySize, SMEM_BYTES);

    __half* hsh = nullptr; cudaGetSymbolAddress((void**)&hsh, g_hsh);
    __half* atth= nullptr; cudaGetSymbolAddress((void**)&atth, g_atth);
    __half* h1h = nullptr; cudaGetSymbolAddress((void**)&h1h, g_h1h);
    __half* wqh = nullptr; cudaGetSymbolAddress((void**)&wqh, g_wqh);
    __half* wkh = nullptr; cudaGetSymbolAddress((void**)&wkh, g_wkh);
    __half* wvh = nullptr; cudaGetSymbolAddress((void**)&wvh, g_wvh);
    __half* woh = nullptr; cudaGetSymbolAddress((void**)&woh, g_woh);
    __half* w1h = nullptr; cudaGetSymbolAddress((void**)&w1h, g_w1h);
    __half* w2h = nullptr; cudaGetSymbolAddress((void**)&w2h, g_w2h);
    __half* hbh = nullptr; cudaGetSymbolAddress((void**)&hbh, g_hbufh);
    float* qf = nullptr;   cudaGetSymbolAddress((void**)&qf, g_q);
    float* kf = nullptr;   cudaGetSymbolAddress((void**)&kf, g_k);
    float* vf = nullptr;   cudaGetSymbolAddress((void**)&vf, g_v);
    float* attf = nullptr; cudaGetSymbolAddress((void**)&attf, g_attn);
    float* projf = nullptr;cudaGetSymbolAddress((void**)&projf, g_proj);
    float* h1f = nullptr;  cudaGetSymbolAddress((void**)&h1f, g_h1);

    zero_cnt<<<1, 32>>>();

    // fp16 conversions (inputs + weights)
    conv16<<<(Tt*Dd/4 + 255)/256, 256>>>(hs, hsh, Tt*Dd/4);
    conv16<<<(Dd*Dd/4 + 255)/256, 256>>>(q_w, wqh, Dd*Dd/4);
    conv16<<<(Dd*Dd/4 + 255)/256, 256>>>(k_w, wkh, Dd*Dd/4);
    conv16<<<(Dd*Dd/4 + 255)/256, 256>>>(v_w, wvh, Dd*Dd/4);
    conv16<<<(Dd*Dd/4 + 255)/256, 256>>>(o_w, woh, Dd*Dd/4);
    conv16<<<(Ee*FFNf*Dd/4 + 255)/256, 256>>>(e_w1, w1h, Ee*FFNf*Dd/4);
    conv16<<<(Ee*Dd*FFNf/4 + 255)/256, 256>>>(e_w2, w2h, Ee*Dd*FFNf/4);

    // QKV projections (HMMA)
    dim3 pg(Tt/128, Dd/128);
    hgemm<0><<<pg, 256, SMEM_BYTES>>>(hsh, wqh, q_b, qf);
    hgemm<0><<<pg, 256, SMEM_BYTES>>>(hsh, wkh, k_b, kf);
    hgemm<0><<<pg, 256, SMEM_BYTES>>>(hsh, wvh, v_b, vf);

    rope_kernel<<<(Tt * Hh * 16 + 255) / 256, 256>>>();
    attn_kernel<<<dim3(Ss / 64, Hh, Bb), 64>>>();

    conv16<<<(Tt*Dd/4 + 255)/256, 256>>>(attf, atth, Tt*Dd/4);
    hgemm<0><<<pg, 256, SMEM_BYTES>>>(atth, woh, o_b, projf);

    add_ln<<<Tt, 128>>>(hs, ln1_g, ln1_b, nullptr, 0);
    conv16<<<(Tt*Dd/4 + 255)/256, 256>>>(h1f, h1h, Tt*Dd/4);

    router_kernel<<<Tt / 4, 128>>>(gatew);
    lb1_kernel<<<Ee, 256>>>();
    lb2_kernel<<<1, 1>>>(out + (out_size - 1));

    // MoE FFN (HMMA, gathered top-2)
    hgemm<1><<<dim3(Tt*2/128, FFNf/128, Ee), 256, SMEM_BYTES>>>(h1h, w1h, e_b1, nullptr);
    hgemm<2><<<dim3(Tt*2/128, Dd/128, Ee), 256, SMEM_BYTES>>>(hbh, w2h, e_b2, nullptr);

    add_ln<<<Tt, 128>>>(nullptr, ln2_g, ln2_b, out, 1);
}

// round 5
// speedup vs baseline: 7.6214x; 1.7825x over previous
#include <cuda_runtime.h>
#include <cuda_fp16.h>
#include <math.h>
#include <stdint.h>

// Problem constants
#define Bb   32
#define Ss   512
#define Dd   512
#define Hh   8
#define Ee   8
#define FFNf 2048
#define Tt   (Bb*Ss)     // 16384 tokens

// ===========================================================================
// Scratch (device globals; no allocations allowed)
// ===========================================================================
__device__ float g_q[Tt*Dd];
__device__ float g_k[Tt*Dd];
__device__ float g_v[Tt*Dd];
__device__ float g_proj[Tt*Dd];
__device__ float g_h1[Tt*Dd];
__device__ float g_moe2[(size_t)Tt*2*Dd];
__device__ float g_router[Tt*Ee];
__device__ int   g_cnt[Ee];
__device__ int   g_tok[Ee*Tt];
__device__ float g_wt[Ee*Tt];
__device__ float g_rsum[Ee];

// fp16 buffers
__device__ __half g_hsh [Tt*Dd];
__device__ __half g_atth[Tt*Dd];          // attention out, token-major [t][512]
__device__ __half g_h1h [Tt*Dd];
__device__ __half g_qh  [Tt*Dd];          // head-major [b][h][s][64]
__device__ __half g_kh  [Tt*Dd];
__device__ __half g_vh  [Tt*Dd];
__device__ __half g_wqh [Dd*Dd];
__device__ __half g_wkh [Dd*Dd];
__device__ __half g_wvh [Dd*Dd];
__device__ __half g_woh [Dd*Dd];
__device__ __half g_w1h [(size_t)Ee*FFNf*Dd];
__device__ __half g_w2h [(size_t)Ee*Dd*FFNf];
__device__ __half g_hbufh[(size_t)Tt*2*FFNf];

// ===========================================================================
__global__ void zero_cnt() { if (threadIdx.x < Ee) g_cnt[threadIdx.x] = 0; }

// fp32 -> fp16 (vectorized, tot multiple of 4)
__global__ void conv16(const float* __restrict__ s, __half* __restrict__ d, int tot4) {
    int i = blockIdx.x * 256 + threadIdx.x;
    if (i >= tot4) return;
    float4 v = ((const float4*)s)[i];
    ((__half2*)d)[2*i]   = __floats2half2_rn(v.x, v.y);
    ((__half2*)d)[2*i+1] = __floats2half2_rn(v.z, v.w);
}

// ===========================================================================
// HMMA helpers
// ===========================================================================
__device__ __forceinline__ uint32_t smem_to_u32(const void* p) {
    uint32_t a;
    asm("{ .reg .u64 t; cvta.to.shared.u64 t, %1; cvt.u32.u64 %0, t; }" : "=r"(a) : "l"(p));
    return a;
}
__device__ __forceinline__ void ldsm_x4(uint32_t& r0, uint32_t& r1, uint32_t& r2, uint32_t& r3, uint32_t a) {
    asm volatile("ldmatrix.sync.aligned.m8n8.x4.shared.b16 {%0,%1,%2,%3}, [%4];"
        : "=r"(r0), "=r"(r1), "=r"(r2), "=r"(r3) : "r"(a));
}
__device__ __forceinline__ void ldsm_x2(uint32_t& r0, uint32_t& r1, uint32_t a) {
    asm volatile("ldmatrix.sync.aligned.m8n8.x2.shared.b16 {%0,%1}, [%2];"
        : "=r"(r0), "=r"(r1) : "r"(a));
}
__device__ __forceinline__ void ldsm_x2_trans(uint32_t& r0, uint32_t& r1, uint32_t a) {
    asm volatile("ldmatrix.sync.aligned.m8n8.x2.trans.shared.b16 {%0,%1}, [%2];"
        : "=r"(r0), "=r"(r1) : "r"(a));
}
__device__ __forceinline__ void mma16816(float* c, uint32_t a0, uint32_t a1, uint32_t a2, uint32_t a3,
                                         uint32_t b0, uint32_t b1) {
    asm volatile("mma.sync.aligned.m16n8k16.row.col.f32.f16.f16.f32 "
        "{%0,%1,%2,%3}, {%4,%5,%6,%7}, {%8,%9}, {%0,%1,%2,%3};"
        : "+f"(c[0]), "+f"(c[1]), "+f"(c[2]), "+f"(c[3])
        : "r"(a0), "r"(a1), "r"(a2), "r"(a3), "r"(b0), "r"(b1));
}
#define CP_ASYNC16(dst, src) \
    asm volatile("cp.async.cg.shared.global [%0], [%1], 16;" :: "r"(dst), "l"(src))
#define CP_COMMIT() asm volatile("cp.async.commit_group;" ::: "memory")
#define CP_WAIT0()  asm volatile("cp.async.wait_group 0;" ::: "memory")

__device__ __forceinline__ uint32_t f2h2(float x, float y) {
    __half2 p = __floats2half2_rn(x, y);
    return *(uint32_t*)&p;
}

// ===========================================================================
// fp16 HMMA GEMM (unchanged from round 4)
// ===========================================================================
#define SMEM_BYTES (2048 + 2*32768)

template<int MODE>
__global__ void __launch_bounds__(256) hgemm(const __half* __restrict__ A,
                                             const __half* __restrict__ Bw,
                                             const float* __restrict__ bias,
                                             float* __restrict__ Cf) {
    constexpr int K  = (MODE == 2) ? FFNf : Dd;
    constexpr int NC = K / 64;
    constexpr int NW = (MODE == 1) ? FFNf : Dd;

    extern __shared__ char smem[];
    uint32_t sb = smem_to_u32(smem);
    int tid = threadIdx.x, wid = tid >> 5, lane = tid & 31;

    int e   = (MODE == 0) ? 0 : blockIdx.z;
    int cnt = (MODE == 0) ? Tt : g_cnt[e];
    int m0  = blockIdx.x * 128;
    if (m0 >= cnt) return;
    int n0  = blockIdx.y * 128;

    const __half* Wp = Bw + (size_t)e * NW * K;
    const float*  bp = bias + (size_t)e * NW;

    int*   s_row  = (int*)(smem);
    int*   s_slot = (int*)(smem + 512);
    float* s_wt   = (float*)(smem + 1024);
    if (tid < 128) {
        int r = m0 + tid;
        if (MODE == 0) { s_row[tid] = r; s_slot[tid] = r; }
        else {
            if (r < cnt) {
                int sl = g_tok[e * Tt + r];
                s_slot[tid] = sl;
                s_row[tid]  = (MODE == 1) ? (sl >> 1) : sl;
                if (MODE == 2) s_wt[tid] = g_wt[e * Tt + r];
            } else { s_slot[tid] = -1; s_row[tid] = 0; if (MODE == 2) s_wt[tid] = 0.f; }
        }
    }
    __syncthreads();

    auto LOAD = [&](int c, int b) {
        int cbase = c * 64;
        uint32_t dstA = sb + 2048 + b * 32768;
        uint32_t dstB = dstA + 16384;
#pragma unroll
        for (int i = 0; i < 4; i++) {
            int u = tid + i * 256;
            int r = u >> 3, c16 = u & 7;
            uint32_t off = (uint32_t)(r * 128 + ((c16 * 16) ^ ((r & 7) << 4)));
            const __half* ga = A + (size_t)s_row[r] * K + cbase + c16 * 8;
            CP_ASYNC16(dstA + off, ga);
            const __half* gb = Wp + (size_t)(n0 + r) * K + cbase + c16 * 8;
            CP_ASYNC16(dstB + off, gb);
        }
        CP_COMMIT();
    };

    LOAD(0, 0);
    CP_WAIT0();
    __syncthreads();

    float acc[4][4][4];
#pragma unroll
    for (int a = 0; a < 4; a++)
#pragma unroll
        for (int b = 0; b < 4; b++)
#pragma unroll
            for (int c = 0; c < 4; c++) acc[a][b][c] = 0.f;

    int wm = (wid & 1) * 64, wn = (wid >> 1) * 32;
    uint32_t swz = (uint32_t)((lane & 7) << 4);
    int arow = wm + (lane & 7) + ((lane >> 3) & 1) * 8;
    uint32_t acolsel = ((lane >> 4) & 1) * 16;
    int brow = wn + (lane & 7);
    uint32_t bcolsel = ((lane >> 3) & 1) * 16;

    for (int c = 0; c < NC; c++) {
        if (c + 1 < NC) LOAD(c + 1, (c + 1) & 1);
        uint32_t sA = sb + 2048 + (c & 1) * 32768;
        uint32_t sB = sA + 16384;
#pragma unroll
        for (int kk = 0; kk < 4; kk++) {
            uint32_t kb = (uint32_t)(kk * 32);
            uint32_t b0[4], b1[4];
#pragma unroll
            for (int nt = 0; nt < 4; nt++) {
                int r = brow + nt * 8;
                uint32_t addr = sB + r * 128 + ((kb + bcolsel) ^ swz);
                ldsm_x2(b0[nt], b1[nt], addr);
            }
#pragma unroll
            for (int mt = 0; mt < 4; mt++) {
                int r = arow + mt * 16;
                uint32_t addr = sA + r * 128 + ((kb + acolsel) ^ swz);
                uint32_t a0, a1, a2, a3;
                ldsm_x4(a0, a1, a2, a3, addr);
#pragma unroll
                for (int nt = 0; nt < 4; nt++)
                    mma16816(acc[mt][nt], a0, a1, a2, a3, b0[nt], b1[nt]);
            }
        }
        if (c + 1 < NC) CP_WAIT0();
        __syncthreads();
    }

    int t4 = lane >> 2, tq = lane & 3;
#pragma unroll
    for (int mt = 0; mt < 4; mt++) {
        int rl0 = wm + mt * 16 + t4;
#pragma unroll
        for (int rr = 0; rr < 2; rr++) {
            int rl = rl0 + rr * 8;
            int slot = s_slot[rl];
            if (slot < 0) continue;
#pragma unroll
            for (int nt = 0; nt < 4; nt++) {
                int gc = n0 + wn + nt * 8 + tq * 2;
                float c0 = acc[mt][nt][rr * 2 + 0];
                float c1 = acc[mt][nt][rr * 2 + 1];
                if (MODE == 0) {
                    float2 o = make_float2(c0 + bp[gc], c1 + bp[gc + 1]);
                    *(float2*)(Cf + (size_t)slot * Dd + gc) = o;
                } else if (MODE == 1) {
                    float x0 = c0 + bp[gc], x1 = c1 + bp[gc + 1];
                    float g0 = 0.5f * x0 * (1.0f + erff(x0 * 0.70710678f));
                    float g1 = 0.5f * x1 * (1.0f + erff(x1 * 0.70710678f));
                    *(__half2*)(g_hbufh + (size_t)slot * FFNf + gc) = __floats2half2_rn(g0, g1);
                } else {
                    float wt = s_wt[rl];
                    float2 o = make_float2(wt * (c0 + bp[gc]), wt * (c1 + bp[gc + 1]));
                    *(float2*)(g_moe2 + (size_t)slot * Dd + gc) = o;
                }
            }
        }
    }
}

// ===========================================================================
// Pack: fp32 q/k/v -> fp16 head-major [b][h][s][64], RoPE fused, q scaled.
// ===========================================================================
__global__ void pack_qkv() {
    int idx = blockIdx.x * 256 + threadIdx.x;
    if (idx >= Tt * 512) return;
    int t = idx >> 9, hd = idx & 511;
    int h = hd >> 6, d = hd & 63;
    int s = t & (Ss - 1), b = t >> 9;
    int src = t * 512 + hd;
    float qv = g_q[src], kv = g_k[src], vv = g_v[src];
    if (d < 32) {
        int i = d & 15;
        float inv = powf(10000.0f, -(float)i / 16.0f);
        float ang = (float)s * inv;
        float sn, cs;
        sincosf(ang, &sn, &cs);
        int other = src + ((d < 16) ? 16 : -16);
        float qo = g_q[other], ko = g_k[other];
        if (d < 16) { qv = qv * cs - qo * sn; kv = kv * cs - ko * sn; }
        else        { qv = qv * cs + qo * sn; kv = kv * cs + ko * sn; }
    }
    size_t dst = ((size_t)(b * Hh + h) * Ss + s) * 64 + d;
    g_qh[dst] = __float2half(qv * 0.125f);
    g_kh[dst] = __float2half(kv);
    g_vh[dst] = __float2half(vv);
}

// ===========================================================================
// HMMA flash attention: block = (64 q-rows, one (b,h)); 4 warps x 16 rows.
// ===========================================================================
__global__ void __launch_bounds__(128) fattn() {
    __shared__ __align__(16) __half Qs[64*64];
    __shared__ __align__(16) __half Ks[2][64*64];
    __shared__ __align__(16) __half Vs[2][64*64];

    int qt = blockIdx.x;          // 0..7
    int bh = blockIdx.y;          // b*8+h
    int tid = threadIdx.x, wid = tid >> 5, lane = tid & 31;

    const __half* Qg = g_qh + ((size_t)bh * Ss + qt * 64) * 64;
    const __half* Kg = g_kh + (size_t)bh * Ss * 64;
    const __half* Vg = g_vh + (size_t)bh * Ss * 64;

    uint32_t sq  = smem_to_u32(Qs);
    uint32_t sk0 = smem_to_u32(Ks);
    uint32_t sv0 = smem_to_u32(Vs);

    // Q tile (64 x 128B), swizzled
#pragma unroll
    for (int i = 0; i < 4; i++) {
        int u = tid + i * 128;
        int r = u >> 3, c16 = u & 7;
        uint32_t off = (uint32_t)(r * 128 + ((c16 * 16) ^ ((r & 7) << 4)));
        CP_ASYNC16(sq + off, Qg + r * 64 + c16 * 8);
    }
    CP_COMMIT();

    auto LOADKV = [&](int j, int b) {
        const __half* kg = Kg + j * 64 * 64;
        const __half* vg = Vg + j * 64 * 64;
        uint32_t dk = sk0 + b * 8192, dv = sv0 + b * 8192;
#pragma unroll
        for (int i = 0; i < 4; i++) {
            int u = tid + i * 128;
            int r = u >> 3, c16 = u & 7;
            uint32_t off = (uint32_t)(r * 128 + ((c16 * 16) ^ ((r & 7) << 4)));
            CP_ASYNC16(dk + off, kg + r * 64 + c16 * 8);
            CP_ASYNC16(dv + off, vg + r * 64 + c16 * 8);
        }
        CP_COMMIT();
    };
    LOADKV(0, 0);
    CP_WAIT0();
    __syncthreads();

    // hoisted Q fragments
    int wm = wid * 16;
    uint32_t swz = (uint32_t)((lane & 7) << 4);
    int arow = wm + (lane & 7) + ((lane >> 3) & 1) * 8;
    uint32_t acolsel = ((lane >> 4) & 1) * 16;
    uint32_t qa[4][4];
#pragma unroll
    for (int kk = 0; kk < 4; kk++)
        ldsm_x4(qa[kk][0], qa[kk][1], qa[kk][2], qa[kk][3],
                sq + arow * 128 + ((kk * 32 + acolsel) ^ swz));

    float o_acc[8][4];
#pragma unroll
    for (int a = 0; a < 8; a++)
#pragma unroll
        for (int b = 0; b < 4; b++) o_acc[a][b] = 0.f;
    float m0 = -1e30f, m1 = -1e30f, l0 = 0.f, l1 = 0.f;

    int brow = lane & 7;
    uint32_t bcolsel = ((lane >> 3) & 1) * 16;
    int vrow_l = lane & 15;

    for (int j = 0; j < 8; j++) {
        if (j + 1 < 8) LOADKV(j + 1, (j + 1) & 1);
        uint32_t sk = sk0 + (j & 1) * 8192;
        uint32_t sv = sv0 + (j & 1) * 8192;

        // S = Q @ K^T  (16 x 64 per warp)
        float s[8][4];
#pragma unroll
        for (int a = 0; a < 8; a++)
#pragma unroll
            for (int b = 0; b < 4; b++) s[a][b] = 0.f;
#pragma unroll
        for (int kk = 0; kk < 4; kk++) {
            uint32_t kb = (uint32_t)(kk * 32);
#pragma unroll
            for (int nt = 0; nt < 8; nt++) {
                uint32_t b0, b1;
                ldsm_x2(b0, b1, sk + (nt * 8 + brow) * 128 + ((kb + bcolsel) ^ swz));
                mma16816(s[nt], qa[kk][0], qa[kk][1], qa[kk][2], qa[kk][3], b0, b1);
            }
        }

        // online softmax (rows r0 = lane>>2, r1 = r0+8)
        float tm0 = -1e30f, tm1 = -1e30f;
#pragma unroll
        for (int nt = 0; nt < 8; nt++) {
            tm0 = fmaxf(tm0, fmaxf(s[nt][0], s[nt][1]));
            tm1 = fmaxf(tm1, fmaxf(s[nt][2], s[nt][3]));
        }
        tm0 = fmaxf(tm0, __shfl_xor_sync(0xffffffffu, tm0, 1));
        tm0 = fmaxf(tm0, __shfl_xor_sync(0xffffffffu, tm0, 2));
        tm1 = fmaxf(tm1, __shfl_xor_sync(0xffffffffu, tm1, 1));
        tm1 = fmaxf(tm1, __shfl_xor_sync(0xffffffffu, tm1, 2));
        float nm0 = fmaxf(m0, tm0), nm1 = fmaxf(m1, tm1);
        float sc0 = __expf(m0 - nm0), sc1 = __expf(m1 - nm1);
        m0 = nm0; m1 = nm1;
        l0 *= sc0; l1 *= sc1;
#pragma unroll
        for (int nt = 0; nt < 8; nt++) {
            o_acc[nt][0] *= sc0; o_acc[nt][1] *= sc0;
            o_acc[nt][2] *= sc1; o_acc[nt][3] *= sc1;
        }
        float sum0 = 0.f, sum1 = 0.f;
#pragma unroll
        for (int nt = 0; nt < 8; nt++) {
            s[nt][0] = __expf(s[nt][0] - m0); s[nt][1] = __expf(s[nt][1] - m0);
            s[nt][2] = __expf(s[nt][2] - m1); s[nt][3] = __expf(s[nt][3] - m1);
            sum0 += s[nt][0] + s[nt][1];
            sum1 += s[nt][2] + s[nt][3];
        }
        sum0 += __shfl_xor_sync(0xffffffffu, sum0, 1);
        sum0 += __shfl_xor_sync(0xffffffffu, sum0, 2);
        sum1 += __shfl_xor_sync(0xffffffffu, sum1, 1);
        sum1 += __shfl_xor_sync(0xffffffffu, sum1, 2);
        l0 += sum0; l1 += sum1;

        // O += P @ V  (P fragments straight from score accumulators)
#pragma unroll
        for (int c = 0; c < 4; c++) {
            uint32_t a0 = f2h2(s[2*c][0],   s[2*c][1]);
            uint32_t a1 = f2h2(s[2*c][2],   s[2*c][3]);
            uint32_t a2 = f2h2(s[2*c+1][0], s[2*c+1][1]);
            uint32_t a3 = f2h2(s[2*c+1][2], s[2*c+1][3]);
            uint32_t vbase = sv + (16 * c + vrow_l) * 128;
#pragma unroll
            for (int nt = 0; nt < 8; nt++) {
                uint32_t b0, b1;
                ldsm_x2_trans(b0, b1, vbase + ((nt * 16) ^ swz));
                mma16816(o_acc[nt], a0, a1, a2, a3, b0, b1);
            }
        }

        CP_WAIT0();
        __syncthreads();
    }

    // write normalized output as fp16 token-major
    float inv0 = 1.0f / l0, inv1 = 1.0f / l1;
    int h = bh & 7, b = bh >> 3;
    int r0 = qt * 64 + wm + (lane >> 2);
    int t0 = b * Ss + r0;
#pragma unroll
    for (int nt = 0; nt < 8; nt++) {
        int col = h * 64 + nt * 8 + (lane & 3) * 2;
        *(__half2*)(g_atth + (size_t)t0 * Dd + col) =
            __floats2half2_rn(o_acc[nt][0] * inv0, o_acc[nt][1] * inv0);
        *(__half2*)(g_atth + (size_t)(t0 + 8) * Dd + col) =
            __floats2half2_rn(o_acc[nt][2] * inv1, o_acc[nt][3] * inv1);
    }
}

// ===========================================================================
// Residual + LayerNorm
// ===========================================================================
__global__ void add_ln(const float* __restrict__ xe,
                       const float* __restrict__ g, const float* __restrict__ bb,
                       float* __restrict__ oe, int mode) {
    int row = blockIdx.x, tid = threadIdx.x;
    size_t base = (size_t)row * Dd;
    float v[4]; float s = 0.0f, sq = 0.0f;
#pragma unroll
    for (int i = 0; i < 4; i++) {
        int c = tid + i * 128;
        float t;
        if (mode == 0) t = xe[base + c] + g_proj[base + c];
        else           t = g_h1[base + c] + (g_moe2[(size_t)(2*row) * Dd + c] + g_moe2[(size_t)(2*row+1) * Dd + c]);
        v[i] = t; s += t; sq += t * t;
    }
#pragma unroll
    for (int off = 16; off; off >>= 1) {
        s  += __shfl_down_sync(0xffffffffu, s,  off);
        sq += __shfl_down_sync(0xffffffffu, sq, off);
    }
    __shared__ float rs[4], rq[4];
    int warp = tid >> 5, lane = tid & 31;
    if (lane == 0) { rs[warp] = s; rq[warp] = sq; }
    __syncthreads();
    if (tid == 0) {
        float S = rs[0] + rs[1] + rs[2] + rs[3];
        float Q = rq[0] + rq[1] + rq[2] + rq[3];
        rs[0] = S; rq[0] = Q;
    }
    __syncthreads();
    float mean = rs[0] * (1.0f / Dd);
    float var  = rq[0] * (1.0f / Dd) - mean * mean;
    float rstd = rsqrtf(var + 1e-5f);
    float* o = (mode == 0) ? g_h1 : oe;
#pragma unroll
    for (int i = 0; i < 4; i++) {
        int c = tid + i * 128;
        o[base + c] = (v[i] - mean) * rstd * g[c] + bb[c];
    }
}

// ===========================================================================
// Router + lb loss
// ===========================================================================
__global__ void router_kernel(const float* __restrict__ gw) {
    int warp = threadIdx.x >> 5, lane = threadIdx.x & 31;
    int t = blockIdx.x * 4 + warp;
    const float* x = g_h1 + (size_t)t * Dd;
    float acc[8] = {};
    for (int d = lane; d < Dd; d += 32) {
        float xv = x[d];
#pragma unroll
        for (int e = 0; e < 8; e++) acc[e] += xv * gw[e * Dd + d];
    }
#pragma unroll
    for (int e = 0; e < 8; e++)
#pragma unroll
        for (int off = 16; off; off >>= 1)
            acc[e] += __shfl_xor_sync(0xffffffffu, acc[e], off);

    if (lane == 0) {
        float mx = acc[0];
#pragma unroll
        for (int e = 1; e < 8; e++) mx = fmaxf(mx, acc[e]);
        float p[8], sm = 0.0f;
#pragma unroll
        for (int e = 0; e < 8; e++) { p[e] = __expf(acc[e] - mx); sm += p[e]; }
        float inv = 1.0f / sm;
#pragma unroll
        for (int e = 0; e < 8; e++) { p[e] *= inv; g_router[t * 8 + e] = p[e]; }
        int i1 = 0;
#pragma unroll
        for (int e = 1; e < 8; e++) if (p[e] > p[i1]) i1 = e;
        int i2 = (i1 == 0) ? 1 : 0;
#pragma unroll
        for (int e = 0; e < 8; e++) if (e != i1 && p[e] > p[i2]) i2 = e;
        float wsum = p[i1] + p[i2];
        int s1 = atomicAdd(&g_cnt[i1], 1);
        g_tok[i1 * Tt + s1] = t * 2;     g_wt[i1 * Tt + s1] = p[i1] / wsum;
        int s2 = atomicAdd(&g_cnt[i2], 1);
        g_tok[i2 * Tt + s2] = t * 2 + 1; g_wt[i2 * Tt + s2] = p[i2] / wsum;
    }
}

__global__ void lb1_kernel() {
    int e = blockIdx.x;
    float p = 0.0f;
    for (int t = threadIdx.x; t < Tt; t += 256) p += g_router[t * 8 + e];
    __shared__ float sm[256];
    sm[threadIdx.x] = p; __syncthreads();
    for (int s = 128; s; s >>= 1) {
        if (threadIdx.x < s) sm[threadIdx.x] += sm[threadIdx.x + s];
        __syncthreads();
    }
    if (threadIdx.x == 0) g_rsum[e] = sm[0];
}
__global__ void lb2_kernel(float* __restrict__ dst) {
    float acc = 0.0f;
#pragma unroll
    for (int e = 0; e < 8; e++) { float m = g_rsum[e] * (1.0f / Tt); acc += m * m; }
    *dst = 8.0f * acc;
}

// ===========================================================================
// Launch
// ===========================================================================
extern "C" void kernel_launch(void* const* d_in, const int* in_sizes, int n_in,
                              void* d_out, int out_size) {
    const float* hs    = (const float*)d_in[0];
    const float* q_w   = (const float*)d_in[1];
    const float* q_b   = (const float*)d_in[2];
    const float* k_w   = (const float*)d_in[3];
    const float* k_b   = (const float*)d_in[4];
    const float* v_w   = (const float*)d_in[5];
    const float* v_b   = (const float*)d_in[6];
    const float* o_w   = (const float*)d_in[7];
    const float* o_b   = (const float*)d_in[8];
    const float* ln1_g = (const float*)d_in[9];
    const float* ln1_b = (const float*)d_in[10];
    const float* gatew = (const float*)d_in[11];
    const float* e_w1  = (const float*)d_in[12];
    const float* e_b1  = (const float*)d_in[13];
    const float* e_w2  = (const float*)d_in[14];
    const float* e_b2  = (const float*)d_in[15];
    const float* ln2_g = (const float*)d_in[16];
    const float* ln2_b = (const float*)d_in[17];
    float* out = (float*)d_out;

    (void)in_sizes; (void)n_in;

    cudaFuncSetAttribute(hgemm<0>, cudaFuncAttributeMaxDynamicSharedMemorySize, SMEM_BYTES);
    cudaFuncSetAttribute(hgemm<1>, cudaFuncAttributeMaxDynamicSharedMemorySize, SMEM_BYTES);
    cudaFuncSetAttribute(hgemm<2>, cudaFuncAttributeMaxDynamicSharedMemorySize, SMEM_BYTES);

    __half* hsh = nullptr; cudaGetSymbolAddress((void**)&hsh, g_hsh);
    __half* atth= nullptr; cudaGetSymbolAddress((void**)&atth, g_atth);
    __half* h1h = nullptr; cudaGetSymbolAddress((void**)&h1h, g_h1h);
    __half* wqh = nullptr; cudaGetSymbolAddress((void**)&wqh, g_wqh);
    __half* wkh = nullptr; cudaGetSymbolAddress((void**)&wkh, g_wkh);
    __half* wvh = nullptr; cudaGetSymbolAddress((void**)&wvh, g_wvh);
    __half* woh = nullptr; cudaGetSymbolAddress((void**)&woh, g_woh);
    __half* w1h = nullptr; cudaGetSymbolAddress((void**)&w1h, g_w1h);
    __half* w2h = nullptr; cudaGetSymbolAddress((void**)&w2h, g_w2h);
    __half* hbh = nullptr; cudaGetSymbolAddress((void**)&hbh, g_hbufh);
    float* qf = nullptr;   cudaGetSymbolAddress((void**)&qf, g_q);
    float* kf = nullptr;   cudaGetSymbolAddress((void**)&kf, g_k);
    float* vf = nullptr;   cudaGetSymbolAddress((void**)&vf, g_v);
    float* projf = nullptr;cudaGetSymbolAddress((void**)&projf, g_proj);
    float* h1f = nullptr;  cudaGetSymbolAddress((void**)&h1f, g_h1);

    zero_cnt<<<1, 32>>>();

    // fp16 conversions
    conv16<<<(Tt*Dd/4 + 255)/256, 256>>>(hs, hsh, Tt*Dd/4);
    conv16<<<(Dd*Dd/4 + 255)/256, 256>>>(q_w, wqh, Dd*Dd/4);
    conv16<<<(Dd*Dd/4 + 255)/256, 256>>>(k_w, wkh, Dd*Dd/4);
    conv16<<<(Dd*Dd/4 + 255)/256, 256>>>(v_w, wvh, Dd*Dd/4);
    conv16<<<(Dd*Dd/4 + 255)/256, 256>>>(o_w, woh, Dd*Dd/4);
    conv16<<<(Ee*FFNf*Dd/4 + 255)/256, 256>>>(e_w1, w1h, Ee*FFNf*Dd/4);
    conv16<<<(Ee*Dd*FFNf/4 + 255)/256, 256>>>(e_w2, w2h, Ee*Dd*FFNf/4);

    // QKV projections
    dim3 pg(Tt/128, Dd/128);
    hgemm<0><<<pg, 256, SMEM_BYTES>>>(hsh, wqh, q_b, qf);
    hgemm<0><<<pg, 256, SMEM_BYTES>>>(hsh, wkh, k_b, kf);
    hgemm<0><<<pg, 256, SMEM_BYTES>>>(hsh, wvh, v_b, vf);

    // rope + fp16 head-major pack, then HMMA flash attention
    pack_qkv<<<(Tt*512 + 255)/256, 256>>>();
    fattn<<<dim3(Ss/64, Bb*Hh), 128>>>();

    // output projection (reads fp16 attention output directly)
    hgemm<0><<<pg, 256, SMEM_BYTES>>>(atth, woh, o_b, projf);

    add_ln<<<Tt, 128>>>(hs, ln1_g, ln1_b, nullptr, 0);
    conv16<<<(Tt*Dd/4 + 255)/256, 256>>>(h1f, h1h, Tt*Dd/4);

    router_kernel<<<Tt / 4, 128>>>(gatew);
    lb1_kernel<<<Ee, 256>>>();
    lb2_kernel<<<1, 1>>>(out + (out_size - 1));

    // MoE FFN
    hgemm<1><<<dim3(Tt*2/128, FFNf/128, Ee), 256, SMEM_BYTES>>>(h1h, w1h, e_b1, nullptr);
    hgemm<2><<<dim3(Tt*2/128, Dd/128, Ee), 256, SMEM_BYTES>>>(hbh, w2h, e_b2, nullptr);

    add_ln<<<Tt, 128>>>(nullptr, ln2_g, ln2_b, out, 1);
}